// round 1
// baseline (speedup 1.0000x reference)
#include <cuda_runtime.h>
#include <cstdint>

// PureTransformerVM: the one-hot "neural ALU" collapses to exact integer /
// piecewise-linear arithmetic. See analysis: sum_byte softmax has exactly
// three output values {1, e^-50, e^-100}; gates = one-hot(op); div = guarded
// Newton reciprocal + round with a correction step that absorbs boundary flips.

#define NROWS 32768
#define OUT_COLS 296   // 256 sum_byte + 39 gates + 1 div

// softmax off-values (fp32-rounded). e^-100 is a subnormal (27 * 2^-149).
#define E_M50  1.9287498479639178e-22f
#define E_M100 3.7835058536770485e-44f

static __device__ __forceinline__ int warp_max_i32(int v) {
    return __reduce_max_sync(0xffffffffu, v);
}

// Scan a float4 for a value > 0.5, recording its element index into dst.
#define CHK4(v, idx, dst)                          \
    do {                                           \
        if ((v).x > 0.5f) (dst) = (idx);           \
        if ((v).y > 0.5f) (dst) = (idx) + 1;       \
        if ((v).z > 0.5f) (dst) = (idx) + 2;       \
        if ((v).w > 0.5f) (dst) = (idx) + 3;       \
    } while (0)

__global__ __launch_bounds__(256)
void vm_kernel(const float4* __restrict__ a_oh,
               const float4* __restrict__ b_oh,
               const float4* __restrict__ op_oh,
               const float*  __restrict__ a_f,
               const float*  __restrict__ b_f,
               float* __restrict__ out)
{
    const int gtid = blockIdx.x * blockDim.x + threadIdx.x;
    const int row  = gtid >> 5;
    const int lane = gtid & 31;
    if (row >= NROWS) return;

    // ---- Load one-hot rows (coalesced float4) -------------------------
    const float4* pa = a_oh  + (size_t)row * 64;
    const float4* pb = b_oh  + (size_t)row * 64;
    const float4* po = op_oh + (size_t)row * 64;

    float4 va0 = pa[lane];
    float4 va1 = pa[lane + 32];
    float4 vb0 = pb[lane];
    float4 vb1 = pb[lane + 32];
    // op_idx < 39 always: only the first 40 floats (10 float4) can be hot.
    float4 vo = make_float4(0.f, 0.f, 0.f, 0.f);
    if (lane < 10) vo = po[lane];

    // scalars (broadcast load within warp = 1 sector each)
    const float af = a_f[row];
    const float bf = b_f[row];

    // ---- Argmax via warp max reduce -----------------------------------
    int ia = -1, ib = -1, io = -1;
    const int base = lane * 4;
    CHK4(va0, base,        ia);
    CHK4(va1, base + 128,  ia);
    CHK4(vb0, base,        ib);
    CHK4(vb1, base + 128,  ib);
    CHK4(vo,  base,        io);

    ia = warp_max_i32(ia);
    ib = warp_max_i32(ib);
    io = warp_max_i32(io);

    // ---- sum_byte index: 8-bit add (carry lo->hi, hi carry dropped) ----
    const int sbyte = (ia + ib) & 255;
    const int sh = sbyte >> 4;
    const int sl = sbyte & 15;

    // ---- div path (all lanes redundantly; lockstep => free) -----------
    float sa = (af > 0.f) ? 1.f : ((af < 0.f) ? -1.f : 0.f);
    float sb = (bf > 0.f) ? 1.f : ((bf < 0.f) ? -1.f : 0.f);
    float sg = sa * sb;
    if (sg == 0.f) sg = 1.f;

    const float aa = fabsf(af);
    const float ba = fabsf(bf);

    const float expo = floorf(log2f(ba + 1e-10f));
    const float p2   = exp2f(expo);
    const float norm = fminf(fmaxf(ba / p2, 0.5f), 0.9999f);

    // piecewise-linear seed for 1/norm (64 segments over [0.5, 1.0])
    int seg = (int)floorf((norm - 0.5f) * 128.0f);
    seg = max(0, min(63, seg));
    const float bpl   = 0.5f + (float)seg * 0.0078125f;
    const float vl    = 1.0f / bpl;
    const float vr    = 1.0f / (bpl + 0.0078125f);
    const float slope = (vr - vl) * 128.0f;
    float y = vl + slope * (norm - bpl);

    // two Newton steps: swiglu(a,b) == a*b to ~3e-7 relative
    y = y * (2.0f - norm * y);
    y = y * (2.0f - norm * y);
    y = y / p2;                       // exact (power of two)

    const float result = aa * y;
    float cand = rintf(result);       // round-half-to-even, matches jnp.round
    const float check = cand * ba;
    if (check > aa + 0.5f) cand -= 1.0f;
    const float divres = cand * sg;

    // ---- Write 296 floats = 74 float4 per row (row stride 1184B, 16B ok)
    float4* pout = (float4*)(out + (size_t)row * OUT_COLS);

    #pragma unroll
    for (int k = 0; k < 3; k++) {
        const int q = k * 32 + lane;          // 0..95, valid < 74
        if (q >= 74) break;
        const int c0 = q * 4;
        float4 w;
        float* wp = (float*)&w;
        #pragma unroll
        for (int e = 0; e < 4; e++) {
            const int c = c0 + e;
            float v;
            if (c < 256) {
                const int hi = c >> 4;
                const int lo = c & 15;
                v = (c == sbyte) ? 1.0f
                    : (((hi == sh) || (lo == sl)) ? E_M50 : E_M100);
            } else if (c < 295) {
                v = ((c - 256) == io) ? 1.0f : 0.0f;
            } else {
                v = divres;
            }
            wp[e] = v;
        }
        pout[q] = w;
    }
}

extern "C" void kernel_launch(void* const* d_in, const int* in_sizes, int n_in,
                              void* d_out, int out_size)
{
    (void)in_sizes; (void)n_in; (void)out_size;
    const float4* a_oh  = (const float4*)d_in[0];
    const float4* b_oh  = (const float4*)d_in[1];
    const float4* op_oh = (const float4*)d_in[2];
    const float*  a_f   = (const float*)d_in[3];
    const float*  b_f   = (const float*)d_in[4];
    float* out = (float*)d_out;

    // one warp per row
    const int threads = 256;
    const int blocks  = (NROWS * 32) / threads;   // 4096
    vm_kernel<<<blocks, threads>>>(a_oh, b_oh, op_oh, a_f, b_f, out);
}

// round 2
// speedup vs baseline: 1.0829x; 1.0829x over previous
#include <cuda_runtime.h>
#include <cstdint>

// PureTransformerVM: one-hot "neural ALU" collapsed to exact integer /
// piecewise-linear arithmetic.
//  - sum_byte softmax has exactly 3 output values {1, e^-50, e^-100}
//  - gates = one-hot(op_idx)
//  - div   = PWL seed + 2 Newton steps + round + correction (kept verbatim
//            from the round-1 kernel, which matched the reference exactly)

#define NROWS 32768
#define OUT_COLS 296   // 256 sum_byte + 39 gates + 1 div

// softmax off-values (fp32-rounded). e^-100 is a subnormal (27 * 2^-149).
#define E_M50  1.9287498479639178e-22f
#define E_M100 3.7835058536770485e-44f

// one-hot argmax via dot-product with the column-index vector.
// products and sums are exact in fp32 (values 0/1 times integers < 256).
static __device__ __forceinline__ float dot_idx(float4 v, float c0) {
    return fmaf(v.x, c0,
           fmaf(v.y, c0 + 1.0f,
           fmaf(v.z, c0 + 2.0f,
                v.w * (c0 + 3.0f))));
}

// value pattern of one float4 group (4 consecutive columns) of the sum_byte
// softmax row: winner -> 1.0, shared hi- or lo-nibble -> e^-50, else e^-100.
static __device__ __forceinline__ float4 sum_group(int q, int sbyte, int sh, int sl) {
    const int hi  = q >> 2;
    const int lob = (q & 3) << 2;
    const int cb  = q << 2;
    float4 w;
    float* wp = (float*)&w;
    #pragma unroll
    for (int e = 0; e < 4; e++) {
        float v = ((hi == sh) || ((lob + e) == sl)) ? E_M50 : E_M100;
        v = ((cb + e) == sbyte) ? 1.0f : v;
        wp[e] = v;
    }
    return w;
}

__global__ __launch_bounds__(256)
void vm_kernel(const float4* __restrict__ a_oh,
               const float4* __restrict__ b_oh,
               const float4* __restrict__ op_oh,
               const float*  __restrict__ a_f,
               const float*  __restrict__ b_f,
               float* __restrict__ out)
{
    const int gtid = blockIdx.x * blockDim.x + threadIdx.x;
    const int row  = gtid >> 5;           // grid covers exactly NROWS warps
    const int lane = gtid & 31;

    // ---- Load one-hot rows (coalesced float4, L2-cacheable: inputs are the
    //      re-read working set across graph replays) ----------------------
    const float4* pa = a_oh  + (size_t)row * 64;
    const float4* pb = b_oh  + (size_t)row * 64;
    const float4* po = op_oh + (size_t)row * 64;

    float4 va0 = pa[lane];
    float4 va1 = pa[lane + 32];
    float4 vb0 = pb[lane];
    float4 vb1 = pb[lane + 32];
    // op_idx < 39: only the first 40 floats (10 float4) can be hot.
    float4 vo = make_float4(0.f, 0.f, 0.f, 0.f);
    if (lane < 10) vo = po[lane];

    const float af = a_f[row];
    const float bf = b_f[row];

    // ---- Argmax: index dot-product (fma pipe) + warp add-reduce ---------
    const float c0 = (float)(lane << 2);
    const float ia_f = dot_idx(va0, c0) + dot_idx(va1, c0 + 128.0f);
    const float ib_f = dot_idx(vb0, c0) + dot_idx(vb1, c0 + 128.0f);
    const float io_f = dot_idx(vo,  c0);

    const int ia = __reduce_add_sync(0xffffffffu, (int)ia_f);
    const int ib = __reduce_add_sync(0xffffffffu, (int)ib_f);
    const int io = __reduce_add_sync(0xffffffffu, (int)io_f);

    // ---- sum_byte index: 8-bit add (carry lo->hi, hi carry dropped) -----
    const int sbyte = (ia + ib) & 255;
    const int sh = sbyte >> 4;
    const int sl = sbyte & 15;

    // ---- div path: VERBATIM from round-1 kernel (matched exactly) -------
    float sa = (af > 0.f) ? 1.f : ((af < 0.f) ? -1.f : 0.f);
    float sb = (bf > 0.f) ? 1.f : ((bf < 0.f) ? -1.f : 0.f);
    float sg = sa * sb;
    if (sg == 0.f) sg = 1.f;

    const float aa = fabsf(af);
    const float ba = fabsf(bf);

    const float expo = floorf(log2f(ba + 1e-10f));
    const float p2   = exp2f(expo);
    const float norm = fminf(fmaxf(ba / p2, 0.5f), 0.9999f);

    int seg = (int)floorf((norm - 0.5f) * 128.0f);
    seg = max(0, min(63, seg));
    const float bpl   = 0.5f + (float)seg * 0.0078125f;
    const float vl    = 1.0f / bpl;
    const float vr    = 1.0f / (bpl + 0.0078125f);
    const float slope = (vr - vl) * 128.0f;
    float y = vl + slope * (norm - bpl);

    y = y * (2.0f - norm * y);
    y = y * (2.0f - norm * y);
    y = y / p2;

    const float result = aa * y;
    float cand = rintf(result);
    const float check = cand * ba;
    if (check > aa + 0.5f) cand -= 1.0f;
    const float divres = cand * sg;

    // ---- Write 296 floats = 74 float4 per row, streaming (evict-first) --
    // 64 groups of sum_byte: exactly 2 per lane; 10-group tail on lanes 0-9.
    float4* pout = (float4*)(out + (size_t)row * OUT_COLS);

    __stcs(&pout[lane],      sum_group(lane,      sbyte, sh, sl));
    __stcs(&pout[lane + 32], sum_group(lane + 32, sbyte, sh, sl));

    if (lane < 10) {
        const int g0 = lane << 2;          // gate index of element 0
        float4 w;
        w.x = (g0     == io) ? 1.0f : 0.0f;
        w.y = (g0 + 1 == io) ? 1.0f : 0.0f;
        w.z = (g0 + 2 == io) ? 1.0f : 0.0f;
        w.w = (lane == 9) ? divres : ((g0 + 3 == io) ? 1.0f : 0.0f);
        __stcs(&pout[64 + lane], w);
    }
}

extern "C" void kernel_launch(void* const* d_in, const int* in_sizes, int n_in,
                              void* d_out, int out_size)
{
    (void)in_sizes; (void)n_in; (void)out_size;
    const float4* a_oh  = (const float4*)d_in[0];
    const float4* b_oh  = (const float4*)d_in[1];
    const float4* op_oh = (const float4*)d_in[2];
    const float*  a_f   = (const float*)d_in[3];
    const float*  b_f   = (const float*)d_in[4];
    float* out = (float*)d_out;

    // one warp per row: 32768 warps = 4096 blocks x 256 threads
    vm_kernel<<<4096, 256>>>(a_oh, b_oh, op_oh, a_f, b_f, out);
}